// round 7
// baseline (speedup 1.0000x reference)
#include <cuda_runtime.h>
#include <cuda_bf16.h>
#include <cstdint>

#define TS 47

// ---------------- fp32 scratch ----------------
__device__ __align__(128) float g_features[8192 * 256];
__device__ __align__(128) float g_featw1 [8192 * 512];
__device__ __align__(128) float g_embmx  [6016 * 1536];
__device__ __align__(128) float g_hidw2  [2 * 128 * 512];
__device__ __align__(128) float g_context[128 * 256];
__device__ __align__(128) float g_states [6016 * 512];

// ---------------- bf16 hi/lo pairs ----------------
__device__ __align__(128) __nv_bfloat16 g_img_hi [8192 * 2048], g_img_lo [8192 * 2048];
__device__ __align__(128) __nv_bfloat16 g_wfc_hi [2048 * 256],  g_wfc_lo [2048 * 256];
__device__ __align__(128) __nv_bfloat16 g_feat_hi[8192 * 256],  g_feat_lo[8192 * 256];
__device__ __align__(128) __nv_bfloat16 g_w1_hi  [256 * 512],   g_w1_lo  [256 * 512];
__device__ __align__(128) __nv_bfloat16 g_etok_hi[6016 * 256],  g_etok_lo[6016 * 256];
__device__ __align__(128) __nv_bfloat16 g_gk2_hi [256 * 1536],  g_gk2_lo [256 * 1536];
__device__ __align__(128) __nv_bfloat16 g_st_hi  [6016 * 512],  g_st_lo  [6016 * 512];
__device__ __align__(128) __nv_bfloat16 g_f1w_hi [512 * 512],   g_f1w_lo [512 * 512];
__device__ __align__(128) __nv_bfloat16 g_f1o_hi [6016 * 512],  g_f1o_lo [6016 * 512];
__device__ __align__(128) __nv_bfloat16 g_f2w_hi [512 * 5000],  g_f2w_lo [512 * 5000];

// ---------------- barrier state (monotonic, replay-safe) ----------------
__device__ unsigned g_flags[128];
__device__ unsigned g_release;
__device__ unsigned g_epoch;

// ---------------- helpers ----------------
__device__ __forceinline__ float tanh_apx(float x) {
    float y;
    asm("tanh.approx.f32 %0, %1;" : "=f"(y) : "f"(x));
    return y;
}
__device__ __forceinline__ unsigned ld_acq(const unsigned* p) {
    unsigned v;
    asm volatile("ld.acquire.gpu.global.u32 %0, [%1];" : "=r"(v) : "l"(p));
    return v;
}
__device__ __forceinline__ void st_rel(unsigned* p, unsigned v) {
    asm volatile("st.release.gpu.global.u32 [%0], %1;" :: "l"(p), "r"(v) : "memory");
}
__device__ __forceinline__ void grid_bar2(int bid, int tid, unsigned tgt) {
    __syncthreads();
    if (bid == 0) {
        if (tid > 0 && tid < 128) {
            while ((int)(ld_acq(&g_flags[tid]) - tgt) < 0) { }
        }
        __syncthreads();
        if (tid == 0) st_rel(&g_release, tgt);
    } else {
        if (tid == 0) {
            st_rel(&g_flags[bid], tgt);
            while ((int)(ld_acq(&g_release) - tgt) < 0) { }
        }
        __syncthreads();
    }
}

__device__ __forceinline__ uint32_t smem_u32(const void* p) {
    uint32_t a;
    asm("{ .reg .u64 t; cvta.to.shared.u64 t, %1; cvt.u32.u64 %0, t; }"
        : "=r"(a) : "l"(p));
    return a;
}
__device__ __forceinline__ void ldsm_x4(uint32_t* r, uint32_t addr) {
    asm volatile("ldmatrix.sync.aligned.m8n8.x4.shared.b16 {%0,%1,%2,%3}, [%4];"
        : "=r"(r[0]), "=r"(r[1]), "=r"(r[2]), "=r"(r[3]) : "r"(addr));
}
__device__ __forceinline__ void ldsm_x2t(uint32_t* r, uint32_t addr) {
    asm volatile("ldmatrix.sync.aligned.m8n8.x2.trans.shared.b16 {%0,%1}, [%2];"
        : "=r"(r[0]), "=r"(r[1]) : "r"(addr));
}
__device__ __forceinline__ void mma_bf16(float* c, const uint32_t* a, const uint32_t* b) {
    asm volatile("mma.sync.aligned.m16n8k16.row.col.f32.bf16.bf16.f32 "
        "{%0,%1,%2,%3},{%4,%5,%6,%7},{%8,%9},{%0,%1,%2,%3};"
        : "+f"(c[0]), "+f"(c[1]), "+f"(c[2]), "+f"(c[3])
        : "r"(a[0]), "r"(a[1]), "r"(a[2]), "r"(a[3]), "r"(b[0]), "r"(b[1]));
}
__device__ __forceinline__ uint32_t packbf(__nv_bfloat16 a, __nv_bfloat16 b) {
    __nv_bfloat162 t = __halves2bfloat162(a, b);
    return *(uint32_t*)&t;
}
__device__ __forceinline__ void cpasync16(uint32_t sa, const void* ga, int sz) {
    asm volatile("cp.async.cg.shared.global [%0], [%1], 16, %2;"
                 :: "r"(sa), "l"(ga), "r"(sz) : "memory");
}

// ---------------- fp32 -> bf16 hi/lo convert ----------------
__global__ void cvt_pair(const float* __restrict__ s,
                         __nv_bfloat16* __restrict__ hi,
                         __nv_bfloat16* __restrict__ lo, int n)
{
    int i = (blockIdx.x * 256 + threadIdx.x) * 4;
    if (i >= n) return;
    float4 v = *(const float4*)(s + i);
    __nv_bfloat16 hx = __float2bfloat16(v.x), hy = __float2bfloat16(v.y);
    __nv_bfloat16 hz = __float2bfloat16(v.z), hw = __float2bfloat16(v.w);
    *(uint2*)(hi + i) = make_uint2(packbf(hx, hy), packbf(hz, hw));
    __nv_bfloat16 lx = __float2bfloat16(v.x - __bfloat162float(hx));
    __nv_bfloat16 ly = __float2bfloat16(v.y - __bfloat162float(hy));
    __nv_bfloat16 lz = __float2bfloat16(v.z - __bfloat162float(hz));
    __nv_bfloat16 lw = __float2bfloat16(v.w - __bfloat162float(hw));
    *(uint2*)(lo + i) = make_uint2(packbf(lx, ly), packbf(lz, lw));
}

// ---------------- bf16-pair tensor-core GEMM, cp.async double buffer ----------------
// C[M,N] = act(A@B + bias). A,B as preconverted hi/lo bf16 planes (row-major).
// 128x128 tile, BK=32, 8 warps. M%128==0, K%32==0, N%8==0 (guard per 8).
#define OFF_ALO 10240
#define OFF_BHI 20480
#define OFF_BLO 29184
#define STAGE   37888

__global__ void __launch_bounds__(256, 2) mma_gemm_bf(
    const __nv_bfloat16* __restrict__ Ahi, const __nv_bfloat16* __restrict__ Alo,
    const __nv_bfloat16* __restrict__ Bhi, const __nv_bfloat16* __restrict__ Blo,
    const float* __restrict__ bias, float* __restrict__ C,
    __nv_bfloat16* __restrict__ Chi, __nv_bfloat16* __restrict__ Clo,
    int M, int N, int K, int relu, int remap)
{
    extern __shared__ char smem[];
    const int tid = threadIdx.x;
    const int wid = tid >> 5, lane = tid & 31;
    const int bm = blockIdx.y * 128, bn = blockIdx.x * 128;
    const int wm = (wid >> 2) * 64;
    const int wn = (wid & 3) * 32;
    const uint32_t sbase = smem_u32(smem);

    float acc[4][4][4] = {};
    const int nc = K >> 5;

    auto issue = [&](int k0, int s) {
        uint32_t sb = sbase + s * STAGE;
        #pragma unroll
        for (int i = 0; i < 2; i++) {
            int task = tid + (i << 8);
            int m = task >> 2, k8 = (task & 3) << 3;
            uint32_t sa = sb + m * 80 + (k8 << 1);
            size_t go = (size_t)(bm + m) * K + k0 + k8;
            cpasync16(sa, Ahi + go, 16);
            cpasync16(sa + OFF_ALO, Alo + go, 16);
        }
        #pragma unroll
        for (int i = 0; i < 2; i++) {
            int task = tid + (i << 8);
            int kk = task >> 4, n8 = (task & 15) << 3;
            int gc = bn + n8;
            uint32_t sa = sb + OFF_BHI + kk * 272 + (n8 << 1);
            size_t go = (size_t)(k0 + kk) * N + gc;
            int sz = (gc + 8 <= N) ? 16 : 0;
            cpasync16(sa, Bhi + go, sz);
            cpasync16(sa + (OFF_BLO - OFF_BHI), Blo + go, sz);
        }
        asm volatile("cp.async.commit_group;" ::: "memory");
    };

    issue(0, 0);

    for (int c = 0; c < nc; c++) {
        int cur = c & 1;
        if (c + 1 < nc) {
            issue((c + 1) << 5, cur ^ 1);
            asm volatile("cp.async.wait_group 1;" ::: "memory");
        } else {
            asm volatile("cp.async.wait_group 0;" ::: "memory");
        }
        __syncthreads();

        uint32_t base = sbase + cur * STAGE;
        uint32_t aAhi = base, aAlo = base + OFF_ALO;
        uint32_t aBhi = base + OFF_BHI, aBlo = base + OFF_BLO;

        #pragma unroll
        for (int kk = 0; kk < 2; kk++) {
            int kb = kk * 16;
            uint32_t ahi[4][4], alo[4][4];
            #pragma unroll
            for (int im = 0; im < 4; im++) {
                int row = wm + im * 16 + (lane & 15);
                uint32_t off = row * 80 + kb * 2 + ((lane >> 4) << 4);
                ldsm_x4(ahi[im], aAhi + off);
                ldsm_x4(alo[im], aAlo + off);
            }
            #pragma unroll
            for (int jn = 0; jn < 4; jn++) {
                int n = wn + jn * 8;
                uint32_t off = (kb + (lane & 15)) * 272 + n * 2;
                uint32_t bhi[2], blo[2];
                ldsm_x2t(bhi, aBhi + off);
                ldsm_x2t(blo, aBlo + off);
                #pragma unroll
                for (int im = 0; im < 4; im++) {
                    mma_bf16(acc[im][jn], ahi[im], bhi);
                    mma_bf16(acc[im][jn], alo[im], bhi);
                    mma_bf16(acc[im][jn], ahi[im], blo);
                }
            }
        }
        __syncthreads();
    }

    // epilogue: bias/relu/remap, fp32 and/or bf16-pair outputs
    int tr = lane >> 2, tc = (lane & 3) << 1;
    #pragma unroll
    for (int im = 0; im < 4; im++) {
        #pragma unroll
        for (int half = 0; half < 2; half++) {
            int grow = bm + wm + im * 16 + tr + half * 8;
            size_t ro;
            if (remap) {
                int t = grow >> 7, b = grow & 127;
                ro = ((size_t)b * TS + t) * (size_t)N;
            } else {
                ro = (size_t)grow * (size_t)N;
            }
            #pragma unroll
            for (int jn = 0; jn < 4; jn++) {
                int gc = bn + wn + jn * 8 + tc;
                if (gc < N) {
                    float v0 = acc[im][jn][half * 2 + 0] + bias[gc];
                    float v1 = acc[im][jn][half * 2 + 1] + bias[gc + 1];
                    if (relu) { v0 = fmaxf(v0, 0.f); v1 = fmaxf(v1, 0.f); }
                    if (C) *(float2*)(C + ro + gc) = make_float2(v0, v1);
                    if (Chi) {
                        __nv_bfloat16 h0 = __float2bfloat16(v0);
                        __nv_bfloat16 h1 = __float2bfloat16(v1);
                        *(uint32_t*)(Chi + ro + gc) = packbf(h0, h1);
                        __nv_bfloat16 l0 = __float2bfloat16(v0 - __bfloat162float(h0));
                        __nv_bfloat16 l1 = __float2bfloat16(v1 - __bfloat162float(h1));
                        *(uint32_t*)(Clo + ro + gc) = packbf(l0, l1);
                    }
                }
            }
        }
    }
}

// ---------------- token embedding gather -> bf16 pair ----------------
__global__ void gather_kernel(const int* __restrict__ target,
                              const float* __restrict__ emb)
{
    int row = blockIdx.x;
    int e = threadIdx.x;
    int t = row >> 7, b = row & 127;
    int tok = (t == 0) ? 1 : target[b * 48 + t];
    float v = emb[(size_t)tok * 256 + e];
    __nv_bfloat16 h = __float2bfloat16(v);
    g_etok_hi[(size_t)row * 256 + e] = h;
    g_etok_lo[(size_t)row * 256 + e] = __float2bfloat16(v - __bfloat162float(h));
}

// ---------------- persistent step loop ----------------
__global__ __launch_bounds__(256) void step_loop_kernel(
    const float* __restrict__ W2, const float* __restrict__ V,
    const float* __restrict__ bV, const float* __restrict__ b2,
    const float* __restrict__ gru_k, const float* __restrict__ gru_b)
{
    __shared__ float sm[4096 + 2 * 3072];
    const int bid = blockIdx.x;
    const int tid = threadIdx.x;
    unsigned bar = g_epoch;
    const unsigned bar0 = bar;

    for (int t = 0; t < TS; t++) {
        // ---- Phase A: hidw2 = states[t-1] @ W2 (K-split 2, 32x32 tiles) ----
        if (t > 0) {
            float* As = sm;
            float* Bs = sm + 1024;
            int z  = bid >> 6;
            int rr = bid & 63;
            int bm = (rr >> 4) * 32;
            int bn = (rr & 15) * 32;
            const float* A = g_states + (size_t)(t - 1) * 65536;
            float* C = g_hidw2 + z * 65536;
            int kbeg = z * 256;
            int arow = tid >> 3, akc = (tid & 7) * 2;
            int bkr = tid >> 4, bnc = (tid & 15) * 2;
            int tx = tid & 15, ty = tid >> 4;
            float a00 = 0.f, a01 = 0.f, a10 = 0.f, a11 = 0.f;

            float2 ra = *(const float2*)(A + (size_t)(bm + arow) * 512 + kbeg + akc);
            float2 rb = *(const float2*)(W2 + (size_t)(kbeg + bkr) * 512 + bn + bnc);
            As[akc * 32 + arow] = ra.x;
            As[(akc + 1) * 32 + arow] = ra.y;
            Bs[bkr * 32 + bnc] = rb.x;
            Bs[bkr * 32 + bnc + 1] = rb.y;
            __syncthreads();

            for (int c = 0; c < 16; c++) {
                int cur = c & 1;
                if (c + 1 < 16) {
                    int k0 = kbeg + (c + 1) * 16;
                    ra = *(const float2*)(A + (size_t)(bm + arow) * 512 + k0 + akc);
                    rb = *(const float2*)(W2 + (size_t)(k0 + bkr) * 512 + bn + bnc);
                }
                float* Ac = As + cur * 512;
                float* Bc = Bs + cur * 512;
                #pragma unroll
                for (int k = 0; k < 16; k++) {
                    float2 a = *(const float2*)&Ac[k * 32 + ty * 2];
                    float2 b = *(const float2*)&Bc[k * 32 + tx * 2];
                    a00 = fmaf(a.x, b.x, a00); a01 = fmaf(a.x, b.y, a01);
                    a10 = fmaf(a.y, b.x, a10); a11 = fmaf(a.y, b.y, a11);
                }
                if (c + 1 < 16) {
                    int nxt = cur ^ 1;
                    As[nxt * 512 + akc * 32 + arow] = ra.x;
                    As[nxt * 512 + (akc + 1) * 32 + arow] = ra.y;
                    Bs[nxt * 512 + bkr * 32 + bnc] = rb.x;
                    Bs[nxt * 512 + bkr * 32 + bnc + 1] = rb.y;
                    __syncthreads();
                }
            }
            int r0 = bm + ty * 2, c0 = bn + tx * 2;
            C[(size_t)(r0 + 0) * 512 + c0 + 0] = a00;
            C[(size_t)(r0 + 0) * 512 + c0 + 1] = a01;
            C[(size_t)(r0 + 1) * 512 + c0 + 0] = a10;
            C[(size_t)(r0 + 1) * 512 + c0 + 1] = a11;
            grid_bar2(bid, tid, ++bar);
        }

        // ---- Phase B: Bahdanau attention ----
        {
            float* hw2 = sm;
            float* sV  = sm + 512;
            float* sl  = sm + 1024;
            int b = bid;
            if (t > 0) {
                hw2[tid]       = g_hidw2[b * 512 + tid]       + g_hidw2[65536 + b * 512 + tid]       + b2[tid];
                hw2[tid + 256] = g_hidw2[b * 512 + tid + 256] + g_hidw2[65536 + b * 512 + tid + 256] + b2[tid + 256];
            } else {
                hw2[tid]       = b2[tid];
                hw2[tid + 256] = b2[tid + 256];
            }
            sV[tid]       = V[tid];
            sV[tid + 256] = V[tid + 256];
            __syncthreads();

            int w = tid >> 5, lane = tid & 31;
            #pragma unroll
            for (int p = 0; p < 8; p++) {
                int l = w * 8 + p;
                const float* row = g_featw1 + ((size_t)b * 64 + l) * 512;
                float a = 0.f;
                #pragma unroll
                for (int j = 0; j < 16; j++) {
                    int u = lane + j * 32;
                    float s = tanh_apx(row[u] + hw2[u]);
                    a = fmaf(s, sV[u], a);
                }
                #pragma unroll
                for (int o = 16; o; o >>= 1) a += __shfl_xor_sync(0xffffffffu, a, o);
                if (lane == 0) sl[l] = a + bV[0];
            }
            __syncthreads();

            if (tid < 32) {
                float v0 = sl[tid], v1 = sl[tid + 32];
                float m = fmaxf(v0, v1);
                #pragma unroll
                for (int o = 16; o; o >>= 1) m = fmaxf(m, __shfl_xor_sync(0xffffffffu, m, o));
                float e0 = __expf(v0 - m), e1 = __expf(v1 - m);
                float s = e0 + e1;
                #pragma unroll
                for (int o = 16; o; o >>= 1) s += __shfl_xor_sync(0xffffffffu, s, o);
                float inv = 1.0f / s;
                sl[tid] = e0 * inv;
                sl[tid + 32] = e1 * inv;
            }
            __syncthreads();

            float c = 0.f;
            #pragma unroll 8
            for (int l = 0; l < 64; l++)
                c = fmaf(sl[l], g_features[((size_t)b * 64 + l) * 256 + tid], c);
            g_context[b * 256 + tid] = c;
        }
        grid_bar2(bid, tid, ++bar);

        // ---- Phase C+D fused: mx = context @ gru_k[:256] + GRU pointwise ----
        {
            float* sA = sm;
            float* sB = sm + 4096;
            int u0 = (bid & 15) * 32;
            int b0 = (bid >> 4) * 16;
            int w = tid >> 5;
            int lane = tid & 31;
            int row0 = 2 * w, row1 = row0 + 1;

            for (int j = tid; j < 1024; j += 256) {
                int r = j >> 6, c4 = j & 63;
                *(float4*)&sA[r * 256 + c4 * 4] =
                    *(const float4*)(g_context + (size_t)(b0 + r) * 256 + c4 * 4);
            }
            int bk = tid >> 3, bu4 = (tid & 7) * 4;
            float4 rb0 = *(const float4*)(gru_k + (size_t)bk * 1536 + u0 + bu4);
            float4 rb1 = *(const float4*)(gru_k + (size_t)bk * 1536 + 512 + u0 + bu4);
            float4 rb2 = *(const float4*)(gru_k + (size_t)bk * 1536 + 1024 + u0 + bu4);
            *(float4*)&sB[bk * 32 + bu4] = rb0;
            *(float4*)&sB[1024 + bk * 32 + bu4] = rb1;
            *(float4*)&sB[2048 + bk * 32 + bu4] = rb2;
            __syncthreads();

            float az0 = 0.f, ar0 = 0.f, ah0 = 0.f;
            float az1 = 0.f, ar1 = 0.f, ah1 = 0.f;

            for (int c = 0; c < 8; c++) {
                int cur = c & 1;
                if (c + 1 < 8) {
                    int k0 = (c + 1) * 32;
                    rb0 = *(const float4*)(gru_k + (size_t)(k0 + bk) * 1536 + u0 + bu4);
                    rb1 = *(const float4*)(gru_k + (size_t)(k0 + bk) * 1536 + 512 + u0 + bu4);
                    rb2 = *(const float4*)(gru_k + (size_t)(k0 + bk) * 1536 + 1024 + u0 + bu4);
                }
                const float* Bc = sB + cur * 3072;
                int kb = c * 32;
                #pragma unroll
                for (int k = 0; k < 32; k++) {
                    float bz = Bc[k * 32 + lane];
                    float br = Bc[1024 + k * 32 + lane];
                    float bh = Bc[2048 + k * 32 + lane];
                    float a0 = sA[row0 * 256 + kb + k];
                    float a1 = sA[row1 * 256 + kb + k];
                    az0 = fmaf(a0, bz, az0); ar0 = fmaf(a0, br, ar0); ah0 = fmaf(a0, bh, ah0);
                    az1 = fmaf(a1, bz, az1); ar1 = fmaf(a1, br, ar1); ah1 = fmaf(a1, bh, ah1);
                }
                if (c + 1 < 8) {
                    int nxt = cur ^ 1;
                    *(float4*)&sB[nxt * 3072 + bk * 32 + bu4] = rb0;
                    *(float4*)&sB[nxt * 3072 + 1024 + bk * 32 + bu4] = rb1;
                    *(float4*)&sB[nxt * 3072 + 2048 + bk * 32 + bu4] = rb2;
                    __syncthreads();
                }
            }

            int u = u0 + lane;
            float rz = gru_b[1536 + u];
            float rr = gru_b[2048 + u];
            float rh = gru_b[2560 + u];
            #pragma unroll
            for (int i = 0; i < 2; i++) {
                int b = b0 + row0 + i;
                size_t r = (size_t)t * 128 + b;
                float xz = (i ? az1 : az0) + g_embmx[r * 1536 + u];
                float xr = (i ? ar1 : ar0) + g_embmx[r * 1536 + 512 + u];
                float xh = (i ? ah1 : ah0) + g_embmx[r * 1536 + 1024 + u];
                float z  = 1.f / (1.f + __expf(-(xz + rz)));
                float rg = 1.f / (1.f + __expf(-(xr + rr)));
                float hh = tanh_apx(xh + rg * rh);
                float st = (1.f - z) * hh;
                g_states[r * 512 + u] = st;
                __nv_bfloat16 h = __float2bfloat16(st);
                g_st_hi[r * 512 + u] = h;
                g_st_lo[r * 512 + u] = __float2bfloat16(st - __bfloat162float(h));
            }
        }
        grid_bar2(bid, tid, ++bar);
    }

    if (bid == 0 && tid == 0) g_epoch = bar0 + (unsigned)(3 * TS - 1);
}

// ---------------- launch ----------------
extern "C" void kernel_launch(void* const* d_in, const int* in_sizes, int n_in,
                              void* d_out, int out_size)
{
    const float* img    = (const float*)d_in[0];
    const int*   target = (const int*)  d_in[1];
    const float* W_fc   = (const float*)d_in[2];
    const float* b_fc   = (const float*)d_in[3];
    const float* W1     = (const float*)d_in[4];
    const float* b1     = (const float*)d_in[5];
    const float* W2     = (const float*)d_in[6];
    const float* b2     = (const float*)d_in[7];
    const float* V      = (const float*)d_in[8];
    const float* bV     = (const float*)d_in[9];
    const float* emb    = (const float*)d_in[10];
    const float* gru_k  = (const float*)d_in[11];
    /* d_in[12] = gru_rk : dead (zero GRU state) */
    const float* gru_b  = (const float*)d_in[13];
    const float* fc1_w  = (const float*)d_in[14];
    const float* fc1_b  = (const float*)d_in[15];
    const float* fc2_w  = (const float*)d_in[16];
    const float* fc2_b  = (const float*)d_in[17];
    float* out = (float*)d_out;

    float *features, *featw1, *embmx;
    __nv_bfloat16 *imgH, *imgL, *wfcH, *wfcL, *featH, *featL, *w1H, *w1L;
    __nv_bfloat16 *gk2H, *gk2L, *stH, *stL, *f1wH, *f1wL, *f1oH, *f1oL, *f2wH, *f2wL;
    __nv_bfloat16 *etH, *etL;
    cudaGetSymbolAddress((void**)&features, g_features);
    cudaGetSymbolAddress((void**)&featw1,  g_featw1);
    cudaGetSymbolAddress((void**)&embmx,   g_embmx);
    cudaGetSymbolAddress((void**)&imgH, g_img_hi);  cudaGetSymbolAddress((void**)&imgL, g_img_lo);
    cudaGetSymbolAddress((void**)&wfcH, g_wfc_hi);  cudaGetSymbolAddress((void**)&wfcL, g_wfc_lo);
    cudaGetSymbolAddress((void**)&featH, g_feat_hi);cudaGetSymbolAddress((void**)&featL, g_feat_lo);
    cudaGetSymbolAddress((void**)&w1H, g_w1_hi);    cudaGetSymbolAddress((void**)&w1L, g_w1_lo);
    cudaGetSymbolAddress((void**)&etH, g_etok_hi);  cudaGetSymbolAddress((void**)&etL, g_etok_lo);
    cudaGetSymbolAddress((void**)&gk2H, g_gk2_hi);  cudaGetSymbolAddress((void**)&gk2L, g_gk2_lo);
    cudaGetSymbolAddress((void**)&stH, g_st_hi);    cudaGetSymbolAddress((void**)&stL, g_st_lo);
    cudaGetSymbolAddress((void**)&f1wH, g_f1w_hi);  cudaGetSymbolAddress((void**)&f1wL, g_f1w_lo);
    cudaGetSymbolAddress((void**)&f1oH, g_f1o_hi);  cudaGetSymbolAddress((void**)&f1oL, g_f1o_lo);
    cudaGetSymbolAddress((void**)&f2wH, g_f2w_hi);  cudaGetSymbolAddress((void**)&f2wL, g_f2w_lo);

    const int SMEM_SZ = 2 * STAGE;
    cudaFuncSetAttribute(mma_gemm_bf, cudaFuncAttributeMaxDynamicSharedMemorySize, SMEM_SZ);

    // weight / input converts
    cvt_pair<<<(8192 * 2048 / 4 + 255) / 256, 256>>>(img, imgH, imgL, 8192 * 2048);
    cvt_pair<<<(2048 * 256 / 4 + 255) / 256, 256>>>(W_fc, wfcH, wfcL, 2048 * 256);
    cvt_pair<<<(256 * 512 / 4 + 255) / 256, 256>>>(W1, w1H, w1L, 256 * 512);
    cvt_pair<<<(256 * 1536 / 4 + 255) / 256, 256>>>(gru_k + 256 * 1536, gk2H, gk2L, 256 * 1536);
    cvt_pair<<<(512 * 512 / 4 + 255) / 256, 256>>>(fc1_w, f1wH, f1wL, 512 * 512);
    cvt_pair<<<(512 * 5000 / 4 + 255) / 256, 256>>>(fc2_w, f2wH, f2wL, 512 * 5000);
    gather_kernel<<<6016, 256>>>(target, emb);

    // encoder: features = relu(img @ W_fc + b_fc); emit fp32 + bf16 pair
    mma_gemm_bf<<<dim3(2, 64), 256, SMEM_SZ>>>(imgH, imgL, wfcH, wfcL, b_fc,
                                               features, featH, featL, 8192, 256, 2048, 1, 0);
    // featw1 = features @ W1 + b1
    mma_gemm_bf<<<dim3(4, 64), 256, SMEM_SZ>>>(featH, featL, w1H, w1L, b1,
                                               featw1, nullptr, nullptr, 8192, 512, 256, 0, 0);
    // embmx = embtok @ gru_k[256:] + gru_b[0]
    mma_gemm_bf<<<dim3(12, 47), 256, SMEM_SZ>>>(etH, etL, gk2H, gk2L, gru_b,
                                                embmx, nullptr, nullptr, 6016, 1536, 256, 0, 0);

    step_loop_kernel<<<128, 256>>>(W2, V, bV, b2, gru_k, gru_b);

    // fc1: states @ fc1_w + fc1_b -> bf16 pair only
    mma_gemm_bf<<<dim3(4, 47), 256, SMEM_SZ>>>(stH, stL, f1wH, f1wL, fc1_b,
                                               nullptr, f1oH, f1oL, 6016, 512, 512, 0, 0);
    // fc2: fc1out @ fc2_w + fc2_b -> out (remapped)
    mma_gemm_bf<<<dim3(40, 47), 256, SMEM_SZ>>>(f1oH, f1oL, f2wH, f2wL, fc2_b,
                                                out, nullptr, nullptr, 6016, 5000, 512, 0, 1);
}

// round 8
// speedup vs baseline: 1.1349x; 1.1349x over previous
#include <cuda_runtime.h>
#include <cuda_bf16.h>
#include <cstdint>

#define TS 47

// ---------------- fp32 scratch ----------------
__device__ __align__(128) float g_features[8192 * 256];
__device__ __align__(128) float g_featw1 [8192 * 512];
__device__ __align__(128) float g_embmx  [6016 * 1536];
__device__ __align__(128) float g_hidw2  [2 * 128 * 512];
__device__ __align__(128) float g_context[128 * 256];
__device__ __align__(128) float g_states [6016 * 512];

// ---------------- bf16 hi/lo pairs ----------------
__device__ __align__(128) __nv_bfloat16 g_img_hi [8192 * 2048], g_img_lo [8192 * 2048];
__device__ __align__(128) __nv_bfloat16 g_wfc_hi [2048 * 256],  g_wfc_lo [2048 * 256];
__device__ __align__(128) __nv_bfloat16 g_feat_hi[8192 * 256],  g_feat_lo[8192 * 256];
__device__ __align__(128) __nv_bfloat16 g_w1_hi  [256 * 512],   g_w1_lo  [256 * 512];
__device__ __align__(128) __nv_bfloat16 g_etok_hi[6016 * 256],  g_etok_lo[6016 * 256];
__device__ __align__(128) __nv_bfloat16 g_gk2_hi [256 * 1536],  g_gk2_lo [256 * 1536];
__device__ __align__(128) __nv_bfloat16 g_st_hi  [6016 * 512],  g_st_lo  [6016 * 512];
__device__ __align__(128) __nv_bfloat16 g_f1w_hi [512 * 512],   g_f1w_lo [512 * 512];
__device__ __align__(128) __nv_bfloat16 g_f1o_hi [6016 * 512],  g_f1o_lo [6016 * 512];
__device__ __align__(128) __nv_bfloat16 g_f2w_hi [512 * 5000],  g_f2w_lo [512 * 5000];

// ---------------- barrier state (monotonic, replay-safe) ----------------
__device__ unsigned g_flags[128];
__device__ unsigned g_release;
__device__ unsigned g_epoch;

// ---------------- helpers ----------------
__device__ __forceinline__ float tanh_apx(float x) {
    float y;
    asm("tanh.approx.f32 %0, %1;" : "=f"(y) : "f"(x));
    return y;
}
__device__ __forceinline__ unsigned ld_acq(const unsigned* p) {
    unsigned v;
    asm volatile("ld.acquire.gpu.global.u32 %0, [%1];" : "=r"(v) : "l"(p));
    return v;
}
__device__ __forceinline__ void st_rel(unsigned* p, unsigned v) {
    asm volatile("st.release.gpu.global.u32 [%0], %1;" :: "l"(p), "r"(v) : "memory");
}
__device__ __forceinline__ void grid_bar2(int bid, int tid, unsigned tgt) {
    __syncthreads();
    if (bid == 0) {
        if (tid > 0 && tid < 128) {
            while ((int)(ld_acq(&g_flags[tid]) - tgt) < 0) { }
        }
        __syncthreads();
        if (tid == 0) st_rel(&g_release, tgt);
    } else {
        if (tid == 0) {
            st_rel(&g_flags[bid], tgt);
            while ((int)(ld_acq(&g_release) - tgt) < 0) { }
        }
        __syncthreads();
    }
}

__device__ __forceinline__ uint32_t smem_u32(const void* p) {
    uint32_t a;
    asm("{ .reg .u64 t; cvta.to.shared.u64 t, %1; cvt.u32.u64 %0, t; }"
        : "=r"(a) : "l"(p));
    return a;
}
__device__ __forceinline__ void ldsm_x4(uint32_t* r, uint32_t addr) {
    asm volatile("ldmatrix.sync.aligned.m8n8.x4.shared.b16 {%0,%1,%2,%3}, [%4];"
        : "=r"(r[0]), "=r"(r[1]), "=r"(r[2]), "=r"(r[3]) : "r"(addr));
}
__device__ __forceinline__ void ldsm_x2t(uint32_t* r, uint32_t addr) {
    asm volatile("ldmatrix.sync.aligned.m8n8.x2.trans.shared.b16 {%0,%1}, [%2];"
        : "=r"(r[0]), "=r"(r[1]) : "r"(addr));
}
__device__ __forceinline__ void mma_bf16(float* c, const uint32_t* a, const uint32_t* b) {
    asm volatile("mma.sync.aligned.m16n8k16.row.col.f32.bf16.bf16.f32 "
        "{%0,%1,%2,%3},{%4,%5,%6,%7},{%8,%9},{%0,%1,%2,%3};"
        : "+f"(c[0]), "+f"(c[1]), "+f"(c[2]), "+f"(c[3])
        : "r"(a[0]), "r"(a[1]), "r"(a[2]), "r"(a[3]), "r"(b[0]), "r"(b[1]));
}
__device__ __forceinline__ uint32_t packbf(__nv_bfloat16 a, __nv_bfloat16 b) {
    __nv_bfloat162 t = __halves2bfloat162(a, b);
    return *(uint32_t*)&t;
}
__device__ __forceinline__ void cpasync16(uint32_t sa, const void* ga, int sz) {
    asm volatile("cp.async.cg.shared.global [%0], [%1], 16, %2;"
                 :: "r"(sa), "l"(ga), "r"(sz) : "memory");
}

// ---------------- fp32 -> bf16 hi/lo convert ----------------
__global__ void cvt_pair(const float* __restrict__ s,
                         __nv_bfloat16* __restrict__ hi,
                         __nv_bfloat16* __restrict__ lo, int n)
{
    int i = (blockIdx.x * 256 + threadIdx.x) * 4;
    if (i >= n) return;
    float4 v = *(const float4*)(s + i);
    __nv_bfloat16 hx = __float2bfloat16(v.x), hy = __float2bfloat16(v.y);
    __nv_bfloat16 hz = __float2bfloat16(v.z), hw = __float2bfloat16(v.w);
    *(uint2*)(hi + i) = make_uint2(packbf(hx, hy), packbf(hz, hw));
    __nv_bfloat16 lx = __float2bfloat16(v.x - __bfloat162float(hx));
    __nv_bfloat16 ly = __float2bfloat16(v.y - __bfloat162float(hy));
    __nv_bfloat16 lz = __float2bfloat16(v.z - __bfloat162float(hz));
    __nv_bfloat16 lw = __float2bfloat16(v.w - __bfloat162float(hw));
    *(uint2*)(lo + i) = make_uint2(packbf(lx, ly), packbf(lz, lw));
}

// ---------------- bf16-pair tensor-core GEMM, cp.async double buffer ----------------
#define OFF_ALO 10240
#define OFF_BHI 20480
#define OFF_BLO 29184
#define STAGE   37888

__global__ void __launch_bounds__(256, 2) mma_gemm_bf(
    const __nv_bfloat16* __restrict__ Ahi, const __nv_bfloat16* __restrict__ Alo,
    const __nv_bfloat16* __restrict__ Bhi, const __nv_bfloat16* __restrict__ Blo,
    const float* __restrict__ bias, float* __restrict__ C,
    __nv_bfloat16* __restrict__ Chi, __nv_bfloat16* __restrict__ Clo,
    int M, int N, int K, int relu, int remap)
{
    extern __shared__ char smem[];
    const int tid = threadIdx.x;
    const int wid = tid >> 5, lane = tid & 31;
    const int bm = blockIdx.y * 128, bn = blockIdx.x * 128;
    const int wm = (wid >> 2) * 64;
    const int wn = (wid & 3) * 32;
    const uint32_t sbase = smem_u32(smem);

    float acc[4][4][4] = {};
    const int nc = K >> 5;

    auto issue = [&](int k0, int s) {
        uint32_t sb = sbase + s * STAGE;
        #pragma unroll
        for (int i = 0; i < 2; i++) {
            int task = tid + (i << 8);
            int m = task >> 2, k8 = (task & 3) << 3;
            uint32_t sa = sb + m * 80 + (k8 << 1);
            size_t go = (size_t)(bm + m) * K + k0 + k8;
            cpasync16(sa, Ahi + go, 16);
            cpasync16(sa + OFF_ALO, Alo + go, 16);
        }
        #pragma unroll
        for (int i = 0; i < 2; i++) {
            int task = tid + (i << 8);
            int kk = task >> 4, n8 = (task & 15) << 3;
            int gc = bn + n8;
            uint32_t sa = sb + OFF_BHI + kk * 272 + (n8 << 1);
            size_t go = (size_t)(k0 + kk) * N + gc;
            int sz = (gc + 8 <= N) ? 16 : 0;
            cpasync16(sa, Bhi + go, sz);
            cpasync16(sa + (OFF_BLO - OFF_BHI), Blo + go, sz);
        }
        asm volatile("cp.async.commit_group;" ::: "memory");
    };

    issue(0, 0);

    for (int c = 0; c < nc; c++) {
        int cur = c & 1;
        if (c + 1 < nc) {
            issue((c + 1) << 5, cur ^ 1);
            asm volatile("cp.async.wait_group 1;" ::: "memory");
        } else {
            asm volatile("cp.async.wait_group 0;" ::: "memory");
        }
        __syncthreads();

        uint32_t base = sbase + cur * STAGE;
        uint32_t aAhi = base, aAlo = base + OFF_ALO;
        uint32_t aBhi = base + OFF_BHI, aBlo = base + OFF_BLO;

        #pragma unroll
        for (int kk = 0; kk < 2; kk++) {
            int kb = kk * 16;
            uint32_t ahi[4][4], alo[4][4];
            #pragma unroll
            for (int im = 0; im < 4; im++) {
                int row = wm + im * 16 + (lane & 15);
                uint32_t off = row * 80 + kb * 2 + ((lane >> 4) << 4);
                ldsm_x4(ahi[im], aAhi + off);
                ldsm_x4(alo[im], aAlo + off);
            }
            #pragma unroll
            for (int jn = 0; jn < 4; jn++) {
                int n = wn + jn * 8;
                uint32_t off = (kb + (lane & 15)) * 272 + n * 2;
                uint32_t bhi[2], blo[2];
                ldsm_x2t(bhi, aBhi + off);
                ldsm_x2t(blo, aBlo + off);
                #pragma unroll
                for (int im = 0; im < 4; im++) {
                    mma_bf16(acc[im][jn], ahi[im], bhi);
                    mma_bf16(acc[im][jn], alo[im], bhi);
                    mma_bf16(acc[im][jn], ahi[im], blo);
                }
            }
        }
        __syncthreads();
    }

    int tr = lane >> 2, tc = (lane & 3) << 1;
    #pragma unroll
    for (int im = 0; im < 4; im++) {
        #pragma unroll
        for (int half = 0; half < 2; half++) {
            int grow = bm + wm + im * 16 + tr + half * 8;
            size_t ro;
            if (remap) {
                int t = grow >> 7, b = grow & 127;
                ro = ((size_t)b * TS + t) * (size_t)N;
            } else {
                ro = (size_t)grow * (size_t)N;
            }
            #pragma unroll
            for (int jn = 0; jn < 4; jn++) {
                int gc = bn + wn + jn * 8 + tc;
                if (gc < N) {
                    float v0 = acc[im][jn][half * 2 + 0] + bias[gc];
                    float v1 = acc[im][jn][half * 2 + 1] + bias[gc + 1];
                    if (relu) { v0 = fmaxf(v0, 0.f); v1 = fmaxf(v1, 0.f); }
                    if (C) *(float2*)(C + ro + gc) = make_float2(v0, v1);
                    if (Chi) {
                        __nv_bfloat16 h0 = __float2bfloat16(v0);
                        __nv_bfloat16 h1 = __float2bfloat16(v1);
                        *(uint32_t*)(Chi + ro + gc) = packbf(h0, h1);
                        __nv_bfloat16 l0 = __float2bfloat16(v0 - __bfloat162float(h0));
                        __nv_bfloat16 l1 = __float2bfloat16(v1 - __bfloat162float(h1));
                        *(uint32_t*)(Clo + ro + gc) = packbf(l0, l1);
                    }
                }
            }
        }
    }
}

// ---------------- token embedding gather -> bf16 pair ----------------
__global__ void gather_kernel(const int* __restrict__ target,
                              const float* __restrict__ emb)
{
    int row = blockIdx.x;
    int e = threadIdx.x;
    int t = row >> 7, b = row & 127;
    int tok = (t == 0) ? 1 : target[b * 48 + t];
    float v = emb[(size_t)tok * 256 + e];
    __nv_bfloat16 h = __float2bfloat16(v);
    g_etok_hi[(size_t)row * 256 + e] = h;
    g_etok_lo[(size_t)row * 256 + e] = __float2bfloat16(v - __bfloat162float(h));
}

// ---------------- persistent step loop (featw1/features smem-resident) ----------------
// dynamic smem layout (floats):
//   sFW1  [0      .. 32767]  featw1[bid]  64x512
//   sFEAT [32768 .. 49151]   features[bid] 64x256
//   work  [49152 .. 56319]   phase scratch (A: 2KB staging x2; B: 1088; C: sA 4096 + sB 3072)
__global__ __launch_bounds__(256) void step_loop_kernel(
    const float* __restrict__ W2, const float* __restrict__ V,
    const float* __restrict__ bV, const float* __restrict__ b2,
    const float* __restrict__ gru_k, const float* __restrict__ gru_b)
{
    extern __shared__ float dsm[];
    float* sFW1  = dsm;
    float* sFEAT = dsm + 32768;
    float* work  = dsm + 49152;

    const int bid = blockIdx.x;
    const int tid = threadIdx.x;
    unsigned bar = g_epoch;
    const unsigned bar0 = bar;

    // cache this block's (== batch element's) featw1 + features for all 47 steps
    for (int j = tid; j < 8192; j += 256)
        *(float4*)&sFW1[j * 4] = *(const float4*)(g_featw1 + (size_t)bid * 32768 + j * 4);
    for (int j = tid; j < 4096; j += 256)
        *(float4*)&sFEAT[j * 4] = *(const float4*)(g_features + (size_t)bid * 16384 + j * 4);
    __syncthreads();

    for (int t = 0; t < TS; t++) {
        // ---- Phase A: hidw2 = states[t-1] @ W2 (K-split 2, 32x32 tiles) ----
        if (t > 0) {
            float* As = work;
            float* Bs = work + 1024;
            int z  = bid >> 6;
            int rr = bid & 63;
            int bm = (rr >> 4) * 32;
            int bn = (rr & 15) * 32;
            const float* A = g_states + (size_t)(t - 1) * 65536;
            float* C = g_hidw2 + z * 65536;
            int kbeg = z * 256;
            int arow = tid >> 3, akc = (tid & 7) * 2;
            int bkr = tid >> 4, bnc = (tid & 15) * 2;
            int tx = tid & 15, ty = tid >> 4;
            float a00 = 0.f, a01 = 0.f, a10 = 0.f, a11 = 0.f;

            float2 ra = *(const float2*)(A + (size_t)(bm + arow) * 512 + kbeg + akc);
            float2 rb = *(const float2*)(W2 + (size_t)(kbeg + bkr) * 512 + bn + bnc);
            As[akc * 32 + arow] = ra.x;
            As[(akc + 1) * 32 + arow] = ra.y;
            Bs[bkr * 32 + bnc] = rb.x;
            Bs[bkr * 32 + bnc + 1] = rb.y;
            __syncthreads();

            for (int c = 0; c < 16; c++) {
                int cur = c & 1;
                if (c + 1 < 16) {
                    int k0 = kbeg + (c + 1) * 16;
                    ra = *(const float2*)(A + (size_t)(bm + arow) * 512 + k0 + akc);
                    rb = *(const float2*)(W2 + (size_t)(k0 + bkr) * 512 + bn + bnc);
                }
                float* Ac = As + cur * 512;
                float* Bc = Bs + cur * 512;
                #pragma unroll
                for (int k = 0; k < 16; k++) {
                    float2 a = *(const float2*)&Ac[k * 32 + ty * 2];
                    float2 b = *(const float2*)&Bc[k * 32 + tx * 2];
                    a00 = fmaf(a.x, b.x, a00); a01 = fmaf(a.x, b.y, a01);
                    a10 = fmaf(a.y, b.x, a10); a11 = fmaf(a.y, b.y, a11);
                }
                if (c + 1 < 16) {
                    int nxt = cur ^ 1;
                    As[nxt * 512 + akc * 32 + arow] = ra.x;
                    As[nxt * 512 + (akc + 1) * 32 + arow] = ra.y;
                    Bs[nxt * 512 + bkr * 32 + bnc] = rb.x;
                    Bs[nxt * 512 + bkr * 32 + bnc + 1] = rb.y;
                    __syncthreads();
                }
            }
            int r0 = bm + ty * 2, c0 = bn + tx * 2;
            C[(size_t)(r0 + 0) * 512 + c0 + 0] = a00;
            C[(size_t)(r0 + 0) * 512 + c0 + 1] = a01;
            C[(size_t)(r0 + 1) * 512 + c0 + 0] = a10;
            C[(size_t)(r0 + 1) * 512 + c0 + 1] = a11;
            grid_bar2(bid, tid, ++bar);
        }

        // ---- Phase B: Bahdanau attention (featw1/features from smem) ----
        {
            float* hw2 = work;
            float* sV  = work + 512;
            float* sl  = work + 1024;
            int b = bid;
            if (t > 0) {
                hw2[tid]       = g_hidw2[b * 512 + tid]       + g_hidw2[65536 + b * 512 + tid]       + b2[tid];
                hw2[tid + 256] = g_hidw2[b * 512 + tid + 256] + g_hidw2[65536 + b * 512 + tid + 256] + b2[tid + 256];
            } else {
                hw2[tid]       = b2[tid];
                hw2[tid + 256] = b2[tid + 256];
            }
            sV[tid]       = V[tid];
            sV[tid + 256] = V[tid + 256];
            __syncthreads();

            int w = tid >> 5, lane = tid & 31;
            #pragma unroll
            for (int p = 0; p < 8; p++) {
                int l = w * 8 + p;
                const float* row = sFW1 + l * 512;
                float a = 0.f;
                #pragma unroll
                for (int j = 0; j < 16; j++) {
                    int u = lane + j * 32;
                    float s = tanh_apx(row[u] + hw2[u]);
                    a = fmaf(s, sV[u], a);
                }
                #pragma unroll
                for (int o = 16; o; o >>= 1) a += __shfl_xor_sync(0xffffffffu, a, o);
                if (lane == 0) sl[l] = a + bV[0];
            }
            __syncthreads();

            if (tid < 32) {
                float v0 = sl[tid], v1 = sl[tid + 32];
                float m = fmaxf(v0, v1);
                #pragma unroll
                for (int o = 16; o; o >>= 1) m = fmaxf(m, __shfl_xor_sync(0xffffffffu, m, o));
                float e0 = __expf(v0 - m), e1 = __expf(v1 - m);
                float s = e0 + e1;
                #pragma unroll
                for (int o = 16; o; o >>= 1) s += __shfl_xor_sync(0xffffffffu, s, o);
                float inv = 1.0f / s;
                sl[tid] = e0 * inv;
                sl[tid + 32] = e1 * inv;
            }
            __syncthreads();

            float c = 0.f;
            #pragma unroll 8
            for (int l = 0; l < 64; l++)
                c = fmaf(sl[l], sFEAT[l * 256 + tid], c);
            g_context[b * 256 + tid] = c;
        }
        grid_bar2(bid, tid, ++bar);

        // ---- Phase C+D fused: mx = context @ gru_k[:256] + GRU pointwise ----
        {
            float* sA = work;            // 16 x 256 context tile
            float* sB = work + 4096;     // 3 x 32k x 32u single buffer
            int u0 = (bid & 15) * 32;
            int b0 = (bid >> 4) * 16;
            int w = tid >> 5;
            int lane = tid & 31;
            int row0 = 2 * w, row1 = row0 + 1;

            for (int j = tid; j < 1024; j += 256) {
                int r = j >> 6, c4 = j & 63;
                *(float4*)&sA[r * 256 + c4 * 4] =
                    *(const float4*)(g_context + (size_t)(b0 + r) * 256 + c4 * 4);
            }
            int bk = tid >> 3, bu4 = (tid & 7) * 4;
            float4 rb0 = *(const float4*)(gru_k + (size_t)bk * 1536 + u0 + bu4);
            float4 rb1 = *(const float4*)(gru_k + (size_t)bk * 1536 + 512 + u0 + bu4);
            float4 rb2 = *(const float4*)(gru_k + (size_t)bk * 1536 + 1024 + u0 + bu4);

            float az0 = 0.f, ar0 = 0.f, ah0 = 0.f;
            float az1 = 0.f, ar1 = 0.f, ah1 = 0.f;

            for (int c = 0; c < 8; c++) {
                *(float4*)&sB[bk * 32 + bu4] = rb0;
                *(float4*)&sB[1024 + bk * 32 + bu4] = rb1;
                *(float4*)&sB[2048 + bk * 32 + bu4] = rb2;
                __syncthreads();
                if (c + 1 < 8) {
                    int k0 = (c + 1) * 32;
                    rb0 = *(const float4*)(gru_k + (size_t)(k0 + bk) * 1536 + u0 + bu4);
                    rb1 = *(const float4*)(gru_k + (size_t)(k0 + bk) * 1536 + 512 + u0 + bu4);
                    rb2 = *(const float4*)(gru_k + (size_t)(k0 + bk) * 1536 + 1024 + u0 + bu4);
                }
                int kb = c * 32;
                #pragma unroll
                for (int k = 0; k < 32; k++) {
                    float bz = sB[k * 32 + lane];
                    float br = sB[1024 + k * 32 + lane];
                    float bh = sB[2048 + k * 32 + lane];
                    float a0 = sA[row0 * 256 + kb + k];
                    float a1 = sA[row1 * 256 + kb + k];
                    az0 = fmaf(a0, bz, az0); ar0 = fmaf(a0, br, ar0); ah0 = fmaf(a0, bh, ah0);
                    az1 = fmaf(a1, bz, az1); ar1 = fmaf(a1, br, ar1); ah1 = fmaf(a1, bh, ah1);
                }
                __syncthreads();
            }

            int u = u0 + lane;
            float rz = gru_b[1536 + u];
            float rr = gru_b[2048 + u];
            float rh = gru_b[2560 + u];
            #pragma unroll
            for (int i = 0; i < 2; i++) {
                int b = b0 + row0 + i;
                size_t r = (size_t)t * 128 + b;
                float xz = (i ? az1 : az0) + g_embmx[r * 1536 + u];
                float xr = (i ? ar1 : ar0) + g_embmx[r * 1536 + 512 + u];
                float xh = (i ? ah1 : ah0) + g_embmx[r * 1536 + 1024 + u];
                float z  = 1.f / (1.f + __expf(-(xz + rz)));
                float rg = 1.f / (1.f + __expf(-(xr + rr)));
                float hh = tanh_apx(xh + rg * rh);
                float st = (1.f - z) * hh;
                g_states[r * 512 + u] = st;
                __nv_bfloat16 h = __float2bfloat16(st);
                g_st_hi[r * 512 + u] = h;
                g_st_lo[r * 512 + u] = __float2bfloat16(st - __bfloat162float(h));
            }
        }
        grid_bar2(bid, tid, ++bar);
    }

    if (bid == 0 && tid == 0) g_epoch = bar0 + (unsigned)(3 * TS - 1);
}

// ---------------- launch ----------------
extern "C" void kernel_launch(void* const* d_in, const int* in_sizes, int n_in,
                              void* d_out, int out_size)
{
    const float* img    = (const float*)d_in[0];
    const int*   target = (const int*)  d_in[1];
    const float* W_fc   = (const float*)d_in[2];
    const float* b_fc   = (const float*)d_in[3];
    const float* W1     = (const float*)d_in[4];
    const float* b1     = (const float*)d_in[5];
    const float* W2     = (const float*)d_in[6];
    const float* b2     = (const float*)d_in[7];
    const float* V      = (const float*)d_in[8];
    const float* bV     = (const float*)d_in[9];
    const float* emb    = (const float*)d_in[10];
    const float* gru_k  = (const float*)d_in[11];
    /* d_in[12] = gru_rk : dead (zero GRU state) */
    const float* gru_b  = (const float*)d_in[13];
    const float* fc1_w  = (const float*)d_in[14];
    const float* fc1_b  = (const float*)d_in[15];
    const float* fc2_w  = (const float*)d_in[16];
    const float* fc2_b  = (const float*)d_in[17];
    float* out = (float*)d_out;

    float *features, *featw1, *embmx;
    __nv_bfloat16 *imgH, *imgL, *wfcH, *wfcL, *featH, *featL, *w1H, *w1L;
    __nv_bfloat16 *gk2H, *gk2L, *stH, *stL, *f1wH, *f1wL, *f1oH, *f1oL, *f2wH, *f2wL;
    __nv_bfloat16 *etH, *etL;
    cudaGetSymbolAddress((void**)&features, g_features);
    cudaGetSymbolAddress((void**)&featw1,  g_featw1);
    cudaGetSymbolAddress((void**)&embmx,   g_embmx);
    cudaGetSymbolAddress((void**)&imgH, g_img_hi);  cudaGetSymbolAddress((void**)&imgL, g_img_lo);
    cudaGetSymbolAddress((void**)&wfcH, g_wfc_hi);  cudaGetSymbolAddress((void**)&wfcL, g_wfc_lo);
    cudaGetSymbolAddress((void**)&featH, g_feat_hi);cudaGetSymbolAddress((void**)&featL, g_feat_lo);
    cudaGetSymbolAddress((void**)&w1H, g_w1_hi);    cudaGetSymbolAddress((void**)&w1L, g_w1_lo);
    cudaGetSymbolAddress((void**)&etH, g_etok_hi);  cudaGetSymbolAddress((void**)&etL, g_etok_lo);
    cudaGetSymbolAddress((void**)&gk2H, g_gk2_hi);  cudaGetSymbolAddress((void**)&gk2L, g_gk2_lo);
    cudaGetSymbolAddress((void**)&stH, g_st_hi);    cudaGetSymbolAddress((void**)&stL, g_st_lo);
    cudaGetSymbolAddress((void**)&f1wH, g_f1w_hi);  cudaGetSymbolAddress((void**)&f1wL, g_f1w_lo);
    cudaGetSymbolAddress((void**)&f1oH, g_f1o_hi);  cudaGetSymbolAddress((void**)&f1oL, g_f1o_lo);
    cudaGetSymbolAddress((void**)&f2wH, g_f2w_hi);  cudaGetSymbolAddress((void**)&f2wL, g_f2w_lo);

    const int SMEM_SZ = 2 * STAGE;
    cudaFuncSetAttribute(mma_gemm_bf, cudaFuncAttributeMaxDynamicSharedMemorySize, SMEM_SZ);
    const int STEP_SMEM = 56320 * 4;   // 220KB
    cudaFuncSetAttribute(step_loop_kernel, cudaFuncAttributeMaxDynamicSharedMemorySize, STEP_SMEM);

    // weight / input converts
    cvt_pair<<<(8192 * 2048 / 4 + 255) / 256, 256>>>(img, imgH, imgL, 8192 * 2048);
    cvt_pair<<<(2048 * 256 / 4 + 255) / 256, 256>>>(W_fc, wfcH, wfcL, 2048 * 256);
    cvt_pair<<<(256 * 512 / 4 + 255) / 256, 256>>>(W1, w1H, w1L, 256 * 512);
    cvt_pair<<<(256 * 1536 / 4 + 255) / 256, 256>>>(gru_k + 256 * 1536, gk2H, gk2L, 256 * 1536);
    cvt_pair<<<(512 * 512 / 4 + 255) / 256, 256>>>(fc1_w, f1wH, f1wL, 512 * 512);
    cvt_pair<<<(512 * 5000 / 4 + 255) / 256, 256>>>(fc2_w, f2wH, f2wL, 512 * 5000);
    gather_kernel<<<6016, 256>>>(target, emb);

    // encoder: features = relu(img @ W_fc + b_fc); emit fp32 + bf16 pair
    mma_gemm_bf<<<dim3(2, 64), 256, SMEM_SZ>>>(imgH, imgL, wfcH, wfcL, b_fc,
                                               features, featH, featL, 8192, 256, 2048, 1, 0);
    // featw1 = features @ W1 + b1
    mma_gemm_bf<<<dim3(4, 64), 256, SMEM_SZ>>>(featH, featL, w1H, w1L, b1,
                                               featw1, nullptr, nullptr, 8192, 512, 256, 0, 0);
    // embmx = embtok @ gru_k[256:] + gru_b[0]
    mma_gemm_bf<<<dim3(12, 47), 256, SMEM_SZ>>>(etH, etL, gk2H, gk2L, gru_b,
                                                embmx, nullptr, nullptr, 6016, 1536, 256, 0, 0);

    step_loop_kernel<<<128, 256, STEP_SMEM>>>(W2, V, bV, b2, gru_k, gru_b);

    // fc1: states @ fc1_w + fc1_b -> bf16 pair only
    mma_gemm_bf<<<dim3(4, 47), 256, SMEM_SZ>>>(stH, stL, f1wH, f1wL, fc1_b,
                                               nullptr, f1oH, f1oL, 6016, 512, 512, 0, 0);
    // fc2: fc1out @ fc2_w + fc2_b -> out (remapped)
    mma_gemm_bf<<<dim3(40, 47), 256, SMEM_SZ>>>(f1oH, f1oL, f2wH, f2wL, fc2_b,
                                                out, nullptr, nullptr, 6016, 5000, 512, 0, 1);
}